// round 1
// baseline (speedup 1.0000x reference)
#include <cuda_runtime.h>

// Problem constants (fixed by the reference: B=8192, T=50, D_IN=6, H=128, OUT_LEN=60, D_OUT=2)
#define TENC 50
#define TDEC 60
#define DIN  6
#define DOUT 2
#define H    128
#define G    (4*H)
#define NB   32      // batch elements per block
#define NP   16      // batch pairs per block
#define NTH  256
#define HPAD 17      // padded pair-row length for h (bank-conflict mitigation)

typedef unsigned long long u64;

// ---------- packed f32x2 helpers (Blackwell FFMA2 path) ----------
__device__ __forceinline__ u64 pack2(float x, float y) {
    u64 r;
    asm("mov.b64 %0, {%1, %2};" : "=l"(r) : "r"(__float_as_uint(x)), "r"(__float_as_uint(y)));
    return r;
}
__device__ __forceinline__ void unpack2(u64 v, float &x, float &y) {
    unsigned lo, hi;
    asm("mov.b64 {%0, %1}, %2;" : "=r"(lo), "=r"(hi) : "l"(v));
    x = __uint_as_float(lo);
    y = __uint_as_float(hi);
}
__device__ __forceinline__ void ffma2(u64 &d, u64 a, u64 b) {
    asm("fma.rn.f32x2 %0, %1, %2, %0;" : "+l"(d) : "l"(a), "l"(b));
}

// ---------- fast transcendentals (EX2/RCP based, ~1e-6 rel err) ----------
__device__ __forceinline__ float sigf(float x) {
    return __fdividef(1.0f, 1.0f + __expf(-x));
}
__device__ __forceinline__ float tanhf_fast(float x) {
    return __fdividef(2.0f, 1.0f + __expf(-2.0f * x)) - 1.0f;
}

// Shared memory layout (floats):
//   h2   : [H][HPAD] float2   -> H*HPAD*2
//   c2   : [NP][H]  float2    -> NP*H*2
//   xall : [TENC][DIN][NP] f2 -> TENC*DIN*NP*2
//   inp2 : [DOUT][NP] float2  -> DOUT*NP*2
//   projs: [DOUT*H] float
//   red  : [4*64] float
#define SMEM_FLOATS (H*HPAD*2 + NP*H*2 + TENC*DIN*NP*2 + DOUT*NP*2 + DOUT*H + 4*64)
#define SMEM_BYTES  (SMEM_FLOATS * 4)

// Compute gates = bias + inp @ Wih^T + h @ Whh^T for this thread's 4 rows x 8 pairs.
// inpv points at a [DI][NP] float2 region.
template<int DI>
__device__ __forceinline__ void compute_gates(
    u64 acc[4][8],
    const float* __restrict__ Wih,
    const float* __restrict__ Whh,
    const float bias[4],
    const float2* __restrict__ inpv,
    const float2* __restrict__ h2,
    int u, int p0)
{
#pragma unroll
    for (int m = 0; m < 4; m++) {
        u64 bb = pack2(bias[m], bias[m]);
#pragma unroll
        for (int p = 0; p < 8; p++) acc[m][p] = bb;
    }
    // input projection (small DI)
#pragma unroll
    for (int d = 0; d < DI; d++) {
        u64 xv[8];
#pragma unroll
        for (int p = 0; p < 8; p++)
            xv[p] = *(const u64*)&inpv[d*NP + p0 + p];
#pragma unroll
        for (int m = 0; m < 4; m++) {
            float w = Wih[(u + m*H)*DI + d];
            u64 w2 = pack2(w, w);
#pragma unroll
            for (int p = 0; p < 8; p++) ffma2(acc[m][p], w2, xv[p]);
        }
    }
    // recurrent matvec: 128 k, 4 rows, 8 pairs
#pragma unroll 2
    for (int k4 = 0; k4 < H; k4 += 4) {
        float4 w[4];
#pragma unroll
        for (int m = 0; m < 4; m++)
            w[m] = *(const float4*)(Whh + (u + m*H)*H + k4);
#pragma unroll
        for (int kk = 0; kk < 4; kk++) {
            u64 hv[8];
#pragma unroll
            for (int p = 0; p < 8; p++)
                hv[p] = *(const u64*)&h2[(k4 + kk)*HPAD + p0 + p];
#pragma unroll
            for (int m = 0; m < 4; m++) {
                float ws = (kk == 0) ? w[m].x : (kk == 1) ? w[m].y : (kk == 2) ? w[m].z : w[m].w;
                u64 w2 = pack2(ws, ws);
#pragma unroll
                for (int p = 0; p < 8; p++) ffma2(acc[m][p], w2, hv[p]);
            }
        }
    }
}

// LSTM nonlinearity + state update for this thread's (u, 8 pairs).
__device__ __forceinline__ void lstm_nonlin(
    u64 acc[4][8], float2* __restrict__ c2, float2* __restrict__ h2, int u, int p0)
{
#pragma unroll
    for (int p = 0; p < 8; p++) {
        float i0, i1, f0, f1, g0, g1, o0, o1;
        unpack2(acc[0][p], i0, i1);
        unpack2(acc[1][p], f0, f1);
        unpack2(acc[2][p], g0, g1);
        unpack2(acc[3][p], o0, o1);
        float2 c = c2[(p0 + p)*H + u];
        c.x = sigf(f0)*c.x + sigf(i0)*tanhf_fast(g0);
        c.y = sigf(f1)*c.y + sigf(i1)*tanhf_fast(g1);
        float2 h;
        h.x = sigf(o0)*tanhf_fast(c.x);
        h.y = sigf(o1)*tanhf_fast(c.y);
        c2[(p0 + p)*H + u] = c;
        h2[u*HPAD + p0 + p] = h;
    }
}

__global__ void __launch_bounds__(NTH, 2)
ego_lstm_kernel(const float* __restrict__ x,
                const float* __restrict__ eWih, const float* __restrict__ eWhh,
                const float* __restrict__ eBih, const float* __restrict__ eBhh,
                const float* __restrict__ dWih, const float* __restrict__ dWhh,
                const float* __restrict__ dBih, const float* __restrict__ dBhh,
                const float* __restrict__ pW,   const float* __restrict__ pB,
                float* __restrict__ out)
{
    extern __shared__ float sm[];
    float2* h2    = (float2*)sm;                 // [H][HPAD]
    float2* c2    = h2 + H*HPAD;                 // [NP][H]
    float2* xall  = c2 + NP*H;                   // [TENC][DIN][NP]
    float2* inp2  = xall + TENC*DIN*NP;          // [DOUT][NP]
    float*  projs = (float*)(inp2 + DOUT*NP);    // [DOUT*H]
    float*  red   = projs + DOUT*H;              // [4*64]

    const int tid  = threadIdx.x;
    const int u    = tid & (H - 1);
    const int half = tid >> 7;
    const int p0   = half * 8;
    const int b0   = blockIdx.x * NB;

    // zero h, c state
    for (int i = tid; i < H*HPAD; i += NTH) h2[i] = make_float2(0.f, 0.f);
    for (int i = tid; i < NP*H;  i += NTH) c2[i] = make_float2(0.f, 0.f);

    // stage this block's x chunk into paired smem layout [t][d][pair]
    for (int i = tid; i < NB*TENC*DIN; i += NTH) {
        int b = i / (TENC*DIN);
        int r = i - b*(TENC*DIN);
        int t = r / DIN;
        int d = r - t*DIN;
        float v = x[(size_t)(b0 + b)*(TENC*DIN) + r];
        ((float*)&xall[(t*DIN + d)*NP + (b >> 1)])[b & 1] = v;
    }
    // stage projection weights
    for (int i = tid; i < DOUT*H; i += NTH) projs[i] = pW[i];
    __syncthreads();

    // per-thread fused biases for its 4 gate rows
    float be[4], bd[4];
#pragma unroll
    for (int m = 0; m < 4; m++) {
        int r = u + m*H;
        be[m] = eBih[r] + eBhh[r];
        bd[m] = dBih[r] + dBhh[r];
    }

    u64 acc[4][8];

    // ---------------- encoder: 50 steps ----------------
    for (int t = 0; t < TENC; t++) {
        compute_gates<DIN>(acc, eWih, eWhh, be, &xall[t*DIN*NP], h2, u, p0);
        __syncthreads();                 // all h reads done
        lstm_nonlin(acc, c2, h2, u, p0); // write new h, c (exclusive cells)
        __syncthreads();
    }

    // decoder initial input = x[:, T-1, :2]
    if (tid < 2*NP) {
        int d = tid & 1, p = tid >> 1;
        inp2[d*NP + p] = xall[((TENC - 1)*DIN + d)*NP + p];
    }
    __syncthreads();

    // ---------------- decoder: 60 steps ----------------
    for (int s = 0; s < TDEC; s++) {
        compute_gates<DOUT>(acc, dWih, dWhh, bd, inp2, h2, u, p0);
        __syncthreads();
        lstm_nonlin(acc, c2, h2, u, p0);
        __syncthreads();

        // projection: pred[b][d] = proj_b[d] + sum_u pW[d][u] * h[b][u]
        {
            int gq = tid >> 6;       // 0..3 : k-quarter
            int j  = tid & 63;       // (b_local, d)
            int bl = j >> 1, dd = j & 1;
            float part = 0.f;
            int ub = gq * 32;
#pragma unroll 8
            for (int k = 0; k < 32; k++) {
                int uu = ub + k;
                float hv = ((const float*)&h2[uu*HPAD + (bl >> 1)])[bl & 1];
                part += projs[dd*H + uu] * hv;
            }
            red[gq*64 + j] = part;
        }
        __syncthreads();
        if (tid < 64) {
            int bl = tid >> 1, dd = tid & 1;
            float pr = red[tid] + red[64 + tid] + red[128 + tid] + red[192 + tid] + pB[dd];
            out[(size_t)(b0 + bl)*(TDEC*DOUT) + s*DOUT + dd] = pr;
            ((float*)&inp2[dd*NP + (bl >> 1)])[bl & 1] = pr;   // feedback input
        }
        __syncthreads();
    }
}

extern "C" void kernel_launch(void* const* d_in, const int* in_sizes, int n_in,
                              void* d_out, int out_size)
{
    const float* x    = (const float*)d_in[0];
    const float* eWih = (const float*)d_in[1];
    const float* eWhh = (const float*)d_in[2];
    const float* eBih = (const float*)d_in[3];
    const float* eBhh = (const float*)d_in[4];
    const float* dWih = (const float*)d_in[5];
    const float* dWhh = (const float*)d_in[6];
    const float* dBih = (const float*)d_in[7];
    const float* dBhh = (const float*)d_in[8];
    const float* pW   = (const float*)d_in[9];
    const float* pB   = (const float*)d_in[10];

    int B = in_sizes[0] / (TENC * DIN);
    int grid = B / NB;

    cudaFuncSetAttribute(ego_lstm_kernel,
                         cudaFuncAttributeMaxDynamicSharedMemorySize, SMEM_BYTES);
    ego_lstm_kernel<<<grid, NTH, SMEM_BYTES>>>(
        x, eWih, eWhh, eBih, eBhh, dWih, dWhh, dBih, dBhh, pW, pB, (float*)d_out);
}

// round 2
// speedup vs baseline: 1.5432x; 1.5432x over previous
#include <cuda_runtime.h>

// Problem constants (B=8192, T=50, D_IN=6, H=128, OUT_LEN=60, D_OUT=2)
#define TENC 50
#define TDEC 60
#define DIN  6
#define DOUT 2
#define H    128
#define G    (4*H)
#define NB   32      // batch elements per block
#define NP   16      // batch pairs per block
#define NTH  256

typedef unsigned long long u64;

// ---------------- __device__ scratch (prep-kernel outputs) ----------------
// Whh transposed+k-vectorized: wt4[k4*G + row] = (W[row][4k4], [4k4+1], [4k4+2], [4k4+3])
__device__ float4 g_ewt4[(H/4)*G];
__device__ float4 g_dwt4[(H/4)*G];
__device__ float  g_ewih[DIN*G];    // [d][row]
__device__ float  g_dwih[DOUT*G];   // [d][row]
__device__ float  g_eb[G], g_db[G]; // fused biases

// ---------- packed f32x2 helpers (Blackwell FFMA2 path) ----------
__device__ __forceinline__ u64 pack2(float x, float y) {
    u64 r;
    asm("mov.b64 %0, {%1, %2};" : "=l"(r) : "r"(__float_as_uint(x)), "r"(__float_as_uint(y)));
    return r;
}
__device__ __forceinline__ void unpack2(u64 v, float &x, float &y) {
    unsigned lo, hi;
    asm("mov.b64 {%0, %1}, %2;" : "=r"(lo), "=r"(hi) : "l"(v));
    x = __uint_as_float(lo);
    y = __uint_as_float(hi);
}
__device__ __forceinline__ void ffma2(u64 &d, u64 a, u64 b) {
    asm("fma.rn.f32x2 %0, %1, %2, %0;" : "+l"(d) : "l"(a), "l"(b));
}

// ---------- fast transcendentals ----------
__device__ __forceinline__ float sigf(float x) {
    return __fdividef(1.0f, 1.0f + __expf(-x));
}
__device__ __forceinline__ float tanhf_fast(float x) {
    return __fdividef(2.0f, 1.0f + __expf(-2.0f * x)) - 1.0f;
}

// ---------------- prep kernel: layout transforms (one-time per launch) ----------------
__global__ void prep_kernel(const float* __restrict__ eWih, const float* __restrict__ eWhh,
                            const float* __restrict__ eBih, const float* __restrict__ eBhh,
                            const float* __restrict__ dWih, const float* __restrict__ dWhh,
                            const float* __restrict__ dBih, const float* __restrict__ dBhh)
{
    int i = blockIdx.x * blockDim.x + threadIdx.x;   // 0 .. G*H-1
    if (i < G*H) {
        int row = i / H, k = i % H;
        ((float*)&g_ewt4[(k >> 2)*G + row])[k & 3] = eWhh[i];
        ((float*)&g_dwt4[(k >> 2)*G + row])[k & 3] = dWhh[i];
    }
    if (i < G*DIN)  { int row = i / DIN,  d = i % DIN;  g_ewih[d*G + row] = eWih[i]; }
    if (i < G*DOUT) { int row = i / DOUT, d = i % DOUT; g_dwih[d*G + row] = dWih[i]; }
    if (i < G) { g_eb[i] = eBih[i] + eBhh[i]; g_db[i] = dBih[i] + dBhh[i]; }
}

// Shared memory layout (floats):
//   hpt  : [NP][H] float2   (transposed: pair-major, k contiguous)
//   c2   : [NP][H] float2
//   xall : [TENC][DIN][NP] float2
//   inp2 : [DOUT][NP] float2
//   projs: [DOUT*H] float
//   red  : [4*64] float
#define SMEM_FLOATS (NP*H*2 + NP*H*2 + TENC*DIN*NP*2 + DOUT*NP*2 + DOUT*H + 4*64)
#define SMEM_BYTES  (SMEM_FLOATS * 4)

// gates = bias + inp @ Wih^T + h @ Whh^T for this thread's 4 gate rows x 8 pairs.
template<int DI>
__device__ __forceinline__ void compute_gates(
    u64 acc[4][8],
    const float* __restrict__ wih_t,     // [DI][G]
    const float4* __restrict__ whh_t,    // [H/4][G]
    const float bias[4],
    const float2* __restrict__ inpv,     // [DI][NP]
    const float2* __restrict__ hpt,      // [NP][H]
    int u, int p0)
{
#pragma unroll
    for (int m = 0; m < 4; m++) {
        u64 bb = pack2(bias[m], bias[m]);
#pragma unroll
        for (int p = 0; p < 8; p++) acc[m][p] = bb;
    }
    // input projection (coalesced weight reads from transposed wih)
#pragma unroll
    for (int d = 0; d < DI; d++) {
        u64 xv[8];
#pragma unroll
        for (int p = 0; p < 8; p++)
            xv[p] = *(const u64*)&inpv[d*NP + p0 + p];
#pragma unroll
        for (int m = 0; m < 4; m++) {
            float w = wih_t[d*G + m*H + u];
            u64 w2 = pack2(w, w);
#pragma unroll
            for (int p = 0; p < 8; p++) ffma2(acc[m][p], w2, xv[p]);
        }
    }
    // recurrent matvec: coalesced k-vectorized weights, LDS.128 h (2 k per load)
#pragma unroll 2
    for (int k4 = 0; k4 < H/4; k4++) {
        float4 w[4];
#pragma unroll
        for (int m = 0; m < 4; m++)
            w[m] = whh_t[k4*G + m*H + u];
        // k-sub {0,1}
        {
            u64 wp0[4], wp1[4];
#pragma unroll
            for (int m = 0; m < 4; m++) { wp0[m] = pack2(w[m].x, w[m].x); wp1[m] = pack2(w[m].y, w[m].y); }
#pragma unroll
            for (int p = 0; p < 8; p++) {
                ulonglong2 hv = *(const ulonglong2*)&hpt[(p0 + p)*H + 4*k4];
#pragma unroll
                for (int m = 0; m < 4; m++) { ffma2(acc[m][p], wp0[m], hv.x); ffma2(acc[m][p], wp1[m], hv.y); }
            }
        }
        // k-sub {2,3}
        {
            u64 wp0[4], wp1[4];
#pragma unroll
            for (int m = 0; m < 4; m++) { wp0[m] = pack2(w[m].z, w[m].z); wp1[m] = pack2(w[m].w, w[m].w); }
#pragma unroll
            for (int p = 0; p < 8; p++) {
                ulonglong2 hv = *(const ulonglong2*)&hpt[(p0 + p)*H + 4*k4 + 2];
#pragma unroll
                for (int m = 0; m < 4; m++) { ffma2(acc[m][p], wp0[m], hv.x); ffma2(acc[m][p], wp1[m], hv.y); }
            }
        }
    }
}

// LSTM nonlinearity + state update for this thread's (u, 8 pairs).
__device__ __forceinline__ void lstm_nonlin(
    u64 acc[4][8], float2* __restrict__ c2, float2* __restrict__ hpt, int u, int p0)
{
#pragma unroll
    for (int p = 0; p < 8; p++) {
        float i0, i1, f0, f1, g0, g1, o0, o1;
        unpack2(acc[0][p], i0, i1);
        unpack2(acc[1][p], f0, f1);
        unpack2(acc[2][p], g0, g1);
        unpack2(acc[3][p], o0, o1);
        float2 c = c2[(p0 + p)*H + u];
        c.x = sigf(f0)*c.x + sigf(i0)*tanhf_fast(g0);
        c.y = sigf(f1)*c.y + sigf(i1)*tanhf_fast(g1);
        float2 h;
        h.x = sigf(o0)*tanhf_fast(c.x);
        h.y = sigf(o1)*tanhf_fast(c.y);
        c2[(p0 + p)*H + u] = c;
        hpt[(p0 + p)*H + u] = h;
    }
}

__global__ void __launch_bounds__(NTH, 2)
ego_lstm_kernel(const float* __restrict__ x,
                const float* __restrict__ pW, const float* __restrict__ pB,
                float* __restrict__ out)
{
    extern __shared__ float sm[];
    float2* hpt   = (float2*)sm;                 // [NP][H]
    float2* c2    = hpt + NP*H;                  // [NP][H]
    float2* xall  = c2 + NP*H;                   // [TENC][DIN][NP]
    float2* inp2  = xall + TENC*DIN*NP;          // [DOUT][NP]
    float*  projs = (float*)(inp2 + DOUT*NP);    // [DOUT*H]
    float*  red   = projs + DOUT*H;              // [4*64]

    const int tid  = threadIdx.x;
    const int u    = tid & (H - 1);
    const int half = tid >> 7;
    const int p0   = half * 8;
    const int b0   = blockIdx.x * NB;

    // zero h, c state
    for (int i = tid; i < NP*H; i += NTH) { hpt[i] = make_float2(0.f, 0.f); c2[i] = make_float2(0.f, 0.f); }

    // stage x chunk into paired smem layout [t][d][pair]
    for (int i = tid; i < NB*TENC*DIN; i += NTH) {
        int b = i / (TENC*DIN);
        int r = i - b*(TENC*DIN);
        int t = r / DIN;
        int d = r - t*DIN;
        float v = x[(size_t)(b0 + b)*(TENC*DIN) + r];
        ((float*)&xall[(t*DIN + d)*NP + (b >> 1)])[b & 1] = v;
    }
    for (int i = tid; i < DOUT*H; i += NTH) projs[i] = pW[i];
    __syncthreads();

    // per-thread fused biases for its 4 gate rows
    float be[4], bd[4];
#pragma unroll
    for (int m = 0; m < 4; m++) {
        be[m] = g_eb[u + m*H];
        bd[m] = g_db[u + m*H];
    }

    u64 acc[4][8];

    // ---------------- encoder: 50 steps ----------------
    for (int t = 0; t < TENC; t++) {
        compute_gates<DIN>(acc, g_ewih, g_ewt4, be, &xall[t*DIN*NP], hpt, u, p0);
        __syncthreads();
        lstm_nonlin(acc, c2, hpt, u, p0);
        __syncthreads();
    }

    // decoder initial input = x[:, T-1, :2]
    if (tid < 2*NP) {
        int d = tid & 1, p = tid >> 1;
        inp2[d*NP + p] = xall[((TENC - 1)*DIN + d)*NP + p];
    }
    __syncthreads();

    // ---------------- decoder: 60 steps ----------------
    for (int s = 0; s < TDEC; s++) {
        compute_gates<DOUT>(acc, g_dwih, g_dwt4, bd, inp2, hpt, u, p0);
        __syncthreads();
        lstm_nonlin(acc, c2, hpt, u, p0);
        __syncthreads();

        // projection: pred[b][d] = proj_b[d] + sum_u pW[d][u] * h[b][u]
        {
            int gq = tid >> 6;       // 0..3 : k-quarter
            int j  = tid & 63;       // (b_local, d)
            int bl = j >> 1, dd = j & 1;
            float part = 0.f;
            int ub = gq * 32;
#pragma unroll 8
            for (int k = 0; k < 32; k++) {
                int uu = ub + k;
                float hv = ((const float*)&hpt[(bl >> 1)*H + uu])[bl & 1];
                part += projs[dd*H + uu] * hv;
            }
            red[gq*64 + j] = part;
        }
        __syncthreads();
        if (tid < 64) {
            int bl = tid >> 1, dd = tid & 1;
            float pr = red[tid] + red[64 + tid] + red[128 + tid] + red[192 + tid] + pB[dd];
            out[(size_t)(b0 + bl)*(TDEC*DOUT) + s*DOUT + dd] = pr;
            ((float*)&inp2[dd*NP + (bl >> 1)])[bl & 1] = pr;   // feedback input
        }
        __syncthreads();
    }
}

extern "C" void kernel_launch(void* const* d_in, const int* in_sizes, int n_in,
                              void* d_out, int out_size)
{
    const float* x    = (const float*)d_in[0];
    const float* eWih = (const float*)d_in[1];
    const float* eWhh = (const float*)d_in[2];
    const float* eBih = (const float*)d_in[3];
    const float* eBhh = (const float*)d_in[4];
    const float* dWih = (const float*)d_in[5];
    const float* dWhh = (const float*)d_in[6];
    const float* dBih = (const float*)d_in[7];
    const float* dBhh = (const float*)d_in[8];
    const float* pW   = (const float*)d_in[9];
    const float* pB   = (const float*)d_in[10];

    int B = in_sizes[0] / (TENC * DIN);
    int grid = B / NB;

    prep_kernel<<<(G*H + 255)/256, 256>>>(eWih, eWhh, eBih, eBhh, dWih, dWhh, dBih, dBhh);

    cudaFuncSetAttribute(ego_lstm_kernel,
                         cudaFuncAttributeMaxDynamicSharedMemorySize, SMEM_BYTES);
    ego_lstm_kernel<<<grid, NTH, SMEM_BYTES>>>(x, pW, pB, (float*)d_out);
}